// round 9
// baseline (speedup 1.0000x reference)
#include <cuda_runtime.h>

// AdaptivePooling2D: [16,225,225,256] f32 -> [16,7,7,256] f32 (channels_last)
// Windows [32*o, 32*o+33) both dims, weight 1/1089.
//
// Round-9: r4's rate-optimal main body (8-col groups, 4KB/warp-step,
// compile-time loop, unroll 2, ~37 regs) UNTOUCHED, but restricted to the 31
// interior rows [32*ox+1, 32*ox+32) that belong to exactly one row-window.
// The 8 boundary rows {0,32,...,224} are handled by extra "boundary" CTAs in
// the same launch (blockIdx-selected role, warp-uniform): each reads its row
// once and scatters the row-sum to both adjacent windows. Every input element
// is read EXACTLY once (829.4 MB vs r4's 851 MB); main-loop register profile
// identical to r4 (r7/r8 failed by bloating regs inside the hot loop).

#define BB 16
#define HH 225
#define WW 225
#define C4 64            // 256 channels / 4 (float4)
#define OX 7
#define OY 7
#define NGRP 29          // 28 groups of 8 cols (w 0..223) + 1 group {224}

#define MAIN_THREADS (BB * C4 * NGRP * OX)      // 207,872
#define MAIN_BLOCKS  (MAIN_THREADS / 256)       // 812 (exact)
#define BND_THREADS  (BB * C4 * NGRP * 8)       // 237,568
#define BND_BLOCKS   (BND_THREADS / 256)        // 928 (exact)

__global__ void __launch_bounds__(256)
pool_r9_kernel(const float4* __restrict__ in, float* __restrict__ out)
{
    const float s = 1.0f / (33.0f * 33.0f);
    const size_t rs = (size_t)WW * C4;

    if (blockIdx.x < MAIN_BLOCKS) {
        // ============ MAIN ROLE: 31 interior rows of one window ============
        int idx = blockIdx.x * 256 + threadIdx.x;
        const int c4 = idx & (C4 - 1);
        int t = idx >> 6;
        const int ox  = t % OX;
        t /= OX;
        const int grp = t % NGRP;
        const int b   = t / NGRP;

        const int w0 = grp * 8;
        const int h0 = ox * 32 + 1;          // interior rows only

        const int k    = grp >> 2;
        const int oyP  = (k < OY) ? k : (OY - 1);
        const bool dual = ((grp & 3) == 0) && (grp >= 4) && (grp <= 24);
        const int oyD  = k - 1;

        const float4* __restrict__ p =
            in + ((size_t)(b * HH + h0) * WW + w0) * C4 + c4;

        float4 acc  = make_float4(0.f, 0.f, 0.f, 0.f);
        float4 acc0 = make_float4(0.f, 0.f, 0.f, 0.f);

        if (grp == NGRP - 1) {
            // single column w=224
#pragma unroll 4
            for (int i = 0; i < 31; ++i) {
                float4 v = __ldg(p); p += rs;
                acc.x += v.x; acc.y += v.y; acc.z += v.z; acc.w += v.w;
            }
        } else {
#pragma unroll 2
            for (int i = 0; i < 31; ++i) {
                float4 v0 = __ldg(p + 0 * C4), v1 = __ldg(p + 1 * C4);
                float4 v2 = __ldg(p + 2 * C4), v3 = __ldg(p + 3 * C4);
                float4 v4 = __ldg(p + 4 * C4), v5 = __ldg(p + 5 * C4);
                float4 v6 = __ldg(p + 6 * C4), v7 = __ldg(p + 7 * C4);
                p += rs;
                acc0.x += v0.x; acc0.y += v0.y; acc0.z += v0.z; acc0.w += v0.w;
                acc.x += v0.x + v1.x + v2.x + v3.x + v4.x + v5.x + v6.x + v7.x;
                acc.y += v0.y + v1.y + v2.y + v3.y + v4.y + v5.y + v6.y + v7.y;
                acc.z += v0.z + v1.z + v2.z + v3.z + v4.z + v5.z + v6.z + v7.z;
                acc.w += v0.w + v1.w + v2.w + v3.w + v4.w + v5.w + v6.w + v7.w;
            }
        }

        float* o0 = out + ((((size_t)(b * OX + ox) * OY + oyP) * C4 + c4) << 2);
        atomicAdd(o0 + 0, acc.x * s);
        atomicAdd(o0 + 1, acc.y * s);
        atomicAdd(o0 + 2, acc.z * s);
        atomicAdd(o0 + 3, acc.w * s);
        if (dual) {
            float* o1 = out + ((((size_t)(b * OX + ox) * OY + oyD) * C4 + c4) << 2);
            atomicAdd(o1 + 0, acc0.x * s);
            atomicAdd(o1 + 1, acc0.y * s);
            atomicAdd(o1 + 2, acc0.z * s);
            atomicAdd(o1 + 3, acc0.w * s);
        }
    } else {
        // ========= BOUNDARY ROLE: one shared row h=32j, read once =========
        int idx = (blockIdx.x - MAIN_BLOCKS) * 256 + threadIdx.x;
        const int c4 = idx & (C4 - 1);
        int t = idx >> 6;
        const int j = t & 7;                 // boundary row index 0..7
        t >>= 3;
        const int grp = t % NGRP;
        const int b   = t / NGRP;

        const int w0 = grp * 8;
        const int h  = j * 32;               // rows 0,32,...,224

        const int k    = grp >> 2;
        const int oyP  = (k < OY) ? k : (OY - 1);
        const bool dual = ((grp & 3) == 0) && (grp >= 4) && (grp <= 24);
        const int oyD  = k - 1;

        const float4* __restrict__ p =
            in + ((size_t)(b * HH + h) * WW + w0) * C4 + c4;

        float4 g;   // 8-column row sum
        float4 v0;  // first column (dual scatter)
        if (grp == NGRP - 1) {
            v0 = __ldg(p);
            g = v0;
        } else {
            v0 = __ldg(p + 0 * C4);
            float4 v1 = __ldg(p + 1 * C4), v2 = __ldg(p + 2 * C4);
            float4 v3 = __ldg(p + 3 * C4), v4 = __ldg(p + 4 * C4);
            float4 v5 = __ldg(p + 5 * C4), v6 = __ldg(p + 6 * C4);
            float4 v7 = __ldg(p + 7 * C4);
            g.x = v0.x + v1.x + v2.x + v3.x + v4.x + v5.x + v6.x + v7.x;
            g.y = v0.y + v1.y + v2.y + v3.y + v4.y + v5.y + v6.y + v7.y;
            g.z = v0.z + v1.z + v2.z + v3.z + v4.z + v5.z + v6.z + v7.z;
            g.w = v0.w + v1.w + v2.w + v3.w + v4.w + v5.w + v6.w + v7.w;
        }

        // Row h=32j belongs to window j (if j<=6) and window j-1 (if j>=1).
        const int oxLo = (j >= 1) ? (j - 1) : 0;
        const int oxHi = (j <= 6) ? j : 6;
#pragma unroll 2
        for (int ox = oxLo; ox <= oxHi; ++ox) {
            float* o0 = out + ((((size_t)(b * OX + ox) * OY + oyP) * C4 + c4) << 2);
            atomicAdd(o0 + 0, g.x * s);
            atomicAdd(o0 + 1, g.y * s);
            atomicAdd(o0 + 2, g.z * s);
            atomicAdd(o0 + 3, g.w * s);
            if (dual) {
                float* o1 = out + ((((size_t)(b * OX + ox) * OY + oyD) * C4 + c4) << 2);
                atomicAdd(o1 + 0, v0.x * s);
                atomicAdd(o1 + 1, v0.y * s);
                atomicAdd(o1 + 2, v0.z * s);
                atomicAdd(o1 + 3, v0.w * s);
            }
        }
    }
}

extern "C" void kernel_launch(void* const* d_in, const int* in_sizes, int n_in,
                              void* d_out, int out_size)
{
    (void)in_sizes; (void)n_in;
    const float4* in = (const float4*)d_in[0];
    float* out = (float*)d_out;

    // Output is poisoned (0xAA) by the harness; atomics need zeros.
    cudaMemsetAsync(d_out, 0, (size_t)out_size * sizeof(float));

    pool_r9_kernel<<<MAIN_BLOCKS + BND_BLOCKS, 256>>>(in, out);
}

// round 10
// speedup vs baseline: 1.0772x; 1.0772x over previous
#include <cuda_runtime.h>

// AdaptivePooling2D: [16,225,225,256] f32 -> [16,7,7,256] f32 (channels_last)
// Windows: [32*o, 32*o+33) in both dims, weight 1/1089 combined.
//
// Round-10 = round-4 (best: 122.8us, 6.95 TB/s) with ONE change: inner-loop
// unroll 2 -> 3 (33 = 3*11, exact). Deeper front-batched MLP (~16 -> ~24
// loads in flight/thread) is the only lever that ever exceeded 6.95 TB/s
// (r1 pass-1, full-33 unroll, hit 7.07). r4 is grid-limited (0.69 waves, all
// CTAs resident), so moderate reg growth is free. Everything else identical:
// thread = (b, c4, grp, ox), 8-column x 33-row sub-window, one 4-float atomic
// scatter + one for the shared boundary column. Traffic 851 MB.

#define BB 16
#define HH 225
#define WW 225
#define C4 64            // 256 channels / 4 (float4)
#define OX 7
#define OY 7
#define NGRP 29          // 28 groups of 8 cols (w 0..223) + 1 group {224}

__global__ void __launch_bounds__(128)
pool_grouped_u3_kernel(const float4* __restrict__ in, float* __restrict__ out)
{
    const int N = BB * C4 * NGRP * OX;     // 207,872 threads
    int idx = blockIdx.x * blockDim.x + threadIdx.x;
    if (idx >= N) return;

    const int c4 = idx & (C4 - 1);
    int t = idx >> 6;
    const int ox  = t % OX;
    t /= OX;
    const int grp = t % NGRP;
    const int b   = t / NGRP;

    const int w0 = grp * 8;
    const int h0 = ox * 32;

    // Primary output column window; w=224 (k=7) folds into window 6.
    const int k   = grp >> 2;
    const int oyP = (k < OY) ? k : (OY - 1);
    // First column of this group is a shared boundary column (w = 32k,
    // 1 <= k <= 6): its column-sum also feeds window k-1.
    const bool dual = ((grp & 3) == 0) && (grp >= 4) && (grp <= 24);
    const int oyD = k - 1;

    const float4* __restrict__ p =
        in + ((size_t)(b * HH + h0) * WW + w0) * C4 + c4;
    const size_t rs = (size_t)WW * C4;     // row stride in float4 units

    float4 acc  = make_float4(0.f, 0.f, 0.f, 0.f);  // all columns in group
    float4 acc0 = make_float4(0.f, 0.f, 0.f, 0.f);  // column j=0 only

    if (grp == NGRP - 1) {
        // Last group: single column w=224.
#pragma unroll 11
        for (int i = 0; i < 33; ++i) {
            float4 v = __ldg(p);
            p += rs;
            acc.x += v.x; acc.y += v.y; acc.z += v.z; acc.w += v.w;
        }
    } else {
#pragma unroll 3
        for (int i = 0; i < 33; ++i) {
            float4 v0 = __ldg(p + 0 * C4);
            float4 v1 = __ldg(p + 1 * C4);
            float4 v2 = __ldg(p + 2 * C4);
            float4 v3 = __ldg(p + 3 * C4);
            float4 v4 = __ldg(p + 4 * C4);
            float4 v5 = __ldg(p + 5 * C4);
            float4 v6 = __ldg(p + 6 * C4);
            float4 v7 = __ldg(p + 7 * C4);
            p += rs;

            acc0.x += v0.x; acc0.y += v0.y; acc0.z += v0.z; acc0.w += v0.w;

            acc.x += v0.x + v1.x + v2.x + v3.x + v4.x + v5.x + v6.x + v7.x;
            acc.y += v0.y + v1.y + v2.y + v3.y + v4.y + v5.y + v6.y + v7.y;
            acc.z += v0.z + v1.z + v2.z + v3.z + v4.z + v5.z + v6.z + v7.z;
            acc.w += v0.w + v1.w + v2.w + v3.w + v4.w + v5.w + v6.w + v7.w;
        }
    }

    const float s = 1.0f / (33.0f * 33.0f);

    float* o0 = out + ((((size_t)(b * OX + ox) * OY + oyP) * C4 + c4) << 2);
    atomicAdd(o0 + 0, acc.x * s);
    atomicAdd(o0 + 1, acc.y * s);
    atomicAdd(o0 + 2, acc.z * s);
    atomicAdd(o0 + 3, acc.w * s);

    if (dual) {
        float* o1 = out + ((((size_t)(b * OX + ox) * OY + oyD) * C4 + c4) << 2);
        atomicAdd(o1 + 0, acc0.x * s);
        atomicAdd(o1 + 1, acc0.y * s);
        atomicAdd(o1 + 2, acc0.z * s);
        atomicAdd(o1 + 3, acc0.w * s);
    }
}

extern "C" void kernel_launch(void* const* d_in, const int* in_sizes, int n_in,
                              void* d_out, int out_size)
{
    (void)in_sizes; (void)n_in;
    const float4* in = (const float4*)d_in[0];
    float* out = (float*)d_out;

    // Output is poisoned (0xAA) by the harness; atomics need zeros.
    cudaMemsetAsync(d_out, 0, (size_t)out_size * sizeof(float));

    const int n = BB * C4 * NGRP * OX;     // 207,872
    pool_grouped_u3_kernel<<<(n + 127) / 128, 128>>>(in, out);
}